// round 14
// baseline (speedup 1.0000x reference)
#include <cuda_runtime.h>
#include <cuda_bf16.h>
#include <cstdint>
#include <cstddef>

// ---------------------------------------------------------------------------
// LSTM: B=512, T=512, I=128, H=512, O=128. Gates [g,i,f,o].
// Persistent 128 CTAs, 320 threads: warps 0-7 consumers, warps 8-9 producers.
// CTA tile: M=64 batch rows x N=128 gate-cols (32 h-cols x 4 gates), K=640
// (x chunk 128 + h 512). 8 batch groups x 16 q-CTAs. Weights smem-resident.
// Round-14: retile (16x dup instead of 32x), 1 poller/CTA, per-group counters.
// ---------------------------------------------------------------------------

#define NCTA 128

__device__ __nv_bfloat16  g_wxtb[2048 * 128];            // Wx^T [n][k] bf16
__device__ __nv_bfloat16  g_wht[2048 * 512];             // Wh^T [n][k] bf16
__device__ __nv_bfloat16  g_xb[(size_t)512 * 512 * 128]; // x bf16 [b][t][i]
__device__ __nv_bfloat16  g_h[2][512 * 512];             // ping-pong h
__device__ float          g_hfinal[512 * 512];           // final h fp32
__device__ unsigned       g_barr[32 * 32];               // per-group ctr @ [g*32]

// named barrier ids (0 reserved)
#define RDY0 1
#define FRE0 2
#define RDY1 3
#define FRE1 4
#define RDYX 5
#define FREX 6
#define PBAR 7

// ---------------- PTX helpers ----------------------------------------------
__device__ __forceinline__ unsigned smem_u32(const void* p) {
    return (unsigned)__cvta_generic_to_shared(p);
}
__device__ __forceinline__ void cp16(void* dst_smem, const void* src) {
    asm volatile("cp.async.cg.shared.global [%0], [%1], 16;"
                 :: "r"(smem_u32(dst_smem)), "l"(src) : "memory");
}
__device__ __forceinline__ void cp_commit() {
    asm volatile("cp.async.commit_group;" ::: "memory");
}
template <int N>
__device__ __forceinline__ void cp_wait() {
    asm volatile("cp.async.wait_group %0;" :: "n"(N) : "memory");
}
__device__ __forceinline__ void bsync(int id) {          // all 320 threads
    asm volatile("bar.sync %0, 320;" :: "r"(id) : "memory");
}
__device__ __forceinline__ void barrive(int id) {
    asm volatile("bar.arrive %0, 320;" :: "r"(id) : "memory");
}
__device__ __forceinline__ void bsync_prod() {           // producers only
    asm volatile("bar.sync %0, 64;" :: "r"(PBAR) : "memory");
}
__device__ __forceinline__ void ldm4(unsigned r[4], unsigned addr) {
    asm volatile("ldmatrix.sync.aligned.m8n8.x4.shared.b16 {%0,%1,%2,%3}, [%4];"
                 : "=r"(r[0]), "=r"(r[1]), "=r"(r[2]), "=r"(r[3]) : "r"(addr));
}
__device__ __forceinline__ void mma_bf16(float& d0, float& d1, float& d2, float& d3,
                                         unsigned a0, unsigned a1, unsigned a2, unsigned a3,
                                         unsigned b0, unsigned b1) {
    asm volatile(
        "mma.sync.aligned.m16n8k16.row.col.f32.bf16.bf16.f32 "
        "{%0,%1,%2,%3},{%4,%5,%6,%7},{%8,%9},{%0,%1,%2,%3};"
        : "+f"(d0), "+f"(d1), "+f"(d2), "+f"(d3)
        : "r"(a0), "r"(a1), "r"(a2), "r"(a3), "r"(b0), "r"(b1));
}
__device__ __forceinline__ float tanhfast(float x) {
    float y;
    asm("tanh.approx.f32 %0, %1;" : "=f"(y) : "f"(x));
    return y;
}
__device__ __forceinline__ float fsig(float x) {
    return fmaf(0.5f, tanhfast(0.5f * x), 0.5f);
}

// ---- mma block: 8 k16 iters; A = m16 tile, B = 4 gates x 2 n8-tiles ----
__device__ __forceinline__ void mma_block8(unsigned aAddr, unsigned bAddr,
                                           unsigned gs, float acc[4][2][4]) {
#pragma unroll
    for (int k16 = 0; k16 < 8; k16++) {
        unsigned a[4];
        ldm4(a, aAddr + k16 * 32);
#pragma unroll
        for (int g = 0; g < 4; g++) {
            unsigned b[4];
            ldm4(b, bAddr + g * gs + k16 * 32);
            mma_bf16(acc[g][0][0], acc[g][0][1], acc[g][0][2], acc[g][0][3],
                     a[0], a[1], a[2], a[3], b[0], b[2]);
            mma_bf16(acc[g][1][0], acc[g][1][1], acc[g][1][2], acc[g][1][3],
                     a[0], a[1], a[2], a[3], b[1], b[3]);
        }
    }
}

// ---------------- converts ---------------------------------------------------
__global__ void conv_w(const float* __restrict__ Wx, const float* __restrict__ Wh) {
    int tid = blockIdx.x * blockDim.x + threadIdx.x;
    int stride = gridDim.x * blockDim.x;
    for (int o = tid; o < 2048 * 128; o += stride) {
        int k = o & 127, n = o >> 7;
        g_wxtb[o] = __float2bfloat16(Wx[(size_t)k * 2048 + n]);
    }
    for (int o = tid; o < 2048 * 512; o += stride) {
        int k = o & 511, n = o >> 9;
        g_wht[o] = __float2bfloat16(Wh[(size_t)k * 2048 + n]);
    }
}

__global__ void conv_x(const float* __restrict__ x) {
    const float4* x4 = (const float4*)x;
    size_t N4 = (size_t)512 * 512 * 128 / 4;
    for (size_t o = (size_t)blockIdx.x * blockDim.x + threadIdx.x; o < N4;
         o += (size_t)gridDim.x * blockDim.x) {
        float4 v = x4[o];
        __nv_bfloat162 lo = __floats2bfloat162_rn(v.x, v.y);
        __nv_bfloat162 hi = __floats2bfloat162_rn(v.z, v.w);
        uint2 pk;
        pk.x = *(unsigned*)&lo;
        pk.y = *(unsigned*)&hi;
        *(uint2*)(g_xb + o * 4) = pk;
    }
}

__global__ void reset_k() {
    int tid = blockIdx.x * blockDim.x + threadIdx.x;
    if (tid < 32 * 32) g_barr[tid] = 0u;
    for (int o = tid; o < 512 * 512; o += gridDim.x * blockDim.x)
        g_h[0][o] = __float2bfloat16(0.f);
}

// ---------------- persistent recurrence --------------------------------------
// smem (bytes):
//   Whs [128][520] bf16 : 0      .. 133120
//   Wxs [128][136] bf16 : 133120 .. 167936
//   As  2x[64][136] bf16 : 167936 .. 202752   (2 x 17408)
//   xs  [64][136] bf16  : 202752 .. 220160
#define OFF_WX 133120
#define OFF_A  167936
#define OFF_X  202752
#define AS_BYTES 17408
#define REC_SMEM 220160
__global__ void __launch_bounds__(320, 1) lstm_rec(const float* __restrict__ bias) {
    extern __shared__ char smem[];
    __nv_bfloat16* Whs = (__nv_bfloat16*)smem;
    __nv_bfloat16* Wxs = (__nv_bfloat16*)(smem + OFF_WX);
    __nv_bfloat16* As0 = (__nv_bfloat16*)(smem + OFF_A);
    __nv_bfloat16* xs  = (__nv_bfloat16*)(smem + OFF_X);

    const int tid = threadIdx.x;
    const int lane = tid & 31, warp = tid >> 5;
    const int q = blockIdx.x & 15, grp = blockIdx.x >> 4;
    const int rbase = grp * 64;
    volatile unsigned* barp = (volatile unsigned*)&g_barr[grp << 5];

    // ---- prologue: stage Wh slice, Wx slice, x(0) with all 320 threads ----
    for (int i = tid; i < 8192; i += 320) {          // Whs: 128 rows x 64 ch
        int rowi = i >> 6, ch = i & 63;
        int gate = rowi >> 5, lc = rowi & 31;
        cp16(&Whs[rowi * 520 + ch * 8],
             g_wht + (size_t)(gate * 512 + q * 32 + lc) * 512 + ch * 8);
    }
    for (int i = tid; i < 2048; i += 320) {          // Wxs: 128 rows x 16 ch
        int rowi = i >> 4, ch = i & 15;
        int gate = rowi >> 5, lc = rowi & 31;
        cp16(&Wxs[rowi * 136 + ch * 8],
             g_wxtb + (size_t)(gate * 512 + q * 32 + lc) * 128 + ch * 8);
    }
    for (int i = tid; i < 1024; i += 320) {          // xs(0): 64 rows x 16 ch
        int r = i >> 4, ch = i & 15;
        cp16(&xs[r * 136 + ch * 8],
             g_xb + ((size_t)(rbase + r) * 512 + 0) * 128 + ch * 8);
    }
    cp_commit(); cp_wait<0>(); __syncthreads();

    if (warp < 8) {
        // =================== CONSUMER (warps 0-7) ===================
        const int wm = warp & 3, wn = warp >> 2;        // 16 rows, 64 N-cols each
        const int tr = lane >> 2, tc = (lane & 3) * 2;

        // A ldmatrix address (round-10 formula, M-tile = wm*16)
        const unsigned aoff =
            (unsigned)(wm * 16 + (lane & 7) + ((lane >> 3) & 1) * 8) * 272u +
            (unsigned)((lane >> 4) & 1) * 16u;
        // B ldmatrix: per gate, mats {j0@kk, j1@kk, j0@kk+8, j1@kk+8}
        const unsigned bRow =
            (unsigned)(wn * 16 + (lane & 7) + ((lane >> 3) & 1) * 8);
        const unsigned bCol = (unsigned)((lane >> 4) & 1) * 16u;
        const unsigned sWhB = smem_u32(Whs) + bRow * 1040u + bCol;   // + kc*256
        const unsigned sWxB = smem_u32(Wxs) + bRow * 272u + bCol;
        const unsigned sX  = smem_u32(xs) + aoff;
        const unsigned sA0 = smem_u32(As0) + aoff;
        const unsigned sA1 = sA0 + AS_BYTES;
        const unsigned GS_WH = 32u * 1040u;
        const unsigned GS_WX = 32u * 272u;

        float bz[4][2][2];
        {
#pragma unroll
            for (int g = 0; g < 4; g++)
#pragma unroll
                for (int j = 0; j < 2; j++) {
                    int col = q * 32 + wn * 16 + j * 8 + tc;
                    bz[g][j][0] = bias[g * 512 + col];
                    bz[g][j][1] = bias[g * 512 + col + 1];
                }
        }
        float c[2][4];
#pragma unroll
        for (int j = 0; j < 2; j++)
#pragma unroll
            for (int e = 0; e < 4; e++) c[j][e] = 0.f;

        // pre-arm the h-buffer free barriers (NOT FREX)
        barrive(FRE0); barrive(FRE1);

        for (int t = 0; t < 512; ++t) {
            if (t > 0) bsync(RDYX);
            float acc[4][2][4];
#pragma unroll
            for (int g = 0; g < 4; g++)
#pragma unroll
                for (int j = 0; j < 2; j++) {
                    acc[g][j][0] = bz[g][j][0]; acc[g][j][1] = bz[g][j][1];
                    acc[g][j][2] = bz[g][j][0]; acc[g][j][3] = bz[g][j][1];
                }
            mma_block8(sX, sWxB, GS_WX, acc);
            if (t < 511) barrive(FREX);

            bsync(RDY0); mma_block8(sA0, sWhB,       GS_WH, acc); barrive(FRE0);
            bsync(RDY1); mma_block8(sA1, sWhB + 256, GS_WH, acc); barrive(FRE1);
            bsync(RDY0); mma_block8(sA0, sWhB + 512, GS_WH, acc); barrive(FRE0);
            bsync(RDY1); mma_block8(sA1, sWhB + 768, GS_WH, acc); barrive(FRE1);

            // gates + state update + h writeback
            const int grow = rbase + wm * 16 + tr;
#pragma unroll
            for (int j = 0; j < 2; j++) {
                int hcol = q * 32 + wn * 16 + j * 8 + tc;
                float hv[4];
#pragma unroll
                for (int e = 0; e < 4; e++) {
                    float gv = tanhfast(acc[0][j][e]);
                    float iv = fsig(acc[1][j][e]);
                    float fv = fsig(acc[2][j][e]);
                    float ov = fsig(acc[3][j][e]);
                    float cn = gv * iv + c[j][e] * fv;
                    c[j][e] = cn;
                    hv[e] = tanhfast(cn) * ov;
                }
                if (t < 511) {
                    __nv_bfloat16* hd = g_h[(t + 1) & 1];
                    *(__nv_bfloat162*)(hd + (size_t)grow * 512 + hcol) =
                        __floats2bfloat162_rn(hv[0], hv[1]);
                    *(__nv_bfloat162*)(hd + (size_t)(grow + 8) * 512 + hcol) =
                        __floats2bfloat162_rn(hv[2], hv[3]);
                } else {
                    *(float2*)(g_hfinal + (size_t)grow * 512 + hcol) =
                        make_float2(hv[0], hv[1]);
                    *(float2*)(g_hfinal + (size_t)(grow + 8) * 512 + hcol) =
                        make_float2(hv[2], hv[3]);
                }
            }

            if (t < 511) {
                __syncwarp();
                if (lane == 0) {
                    __threadfence();
                    atomicAdd((unsigned*)barp, 1u);   // 8 warps x 16 CTAs = 128/step
                }
            }
        }
    } else {
        // =================== PRODUCER (warps 8-9) ===================
        const int pid = tid - 256;          // 0..63
        for (int t = 0; t < 512; ++t) {
            if (pid == 0) {                 // single poller per CTA
                unsigned tgt = (unsigned)t * 128u;
                while (*barp < tgt) { }
                __threadfence();
            }
            bsync_prod();                   // broadcast detection to both warps

            const __nv_bfloat16* hsrc = g_h[t & 1] + (size_t)rbase * 512;

            // h0 -> buf0
            bsync(FRE0);
            for (int i = pid; i < 1024; i += 64) {
                int r = i >> 4, ch = i & 15;
                cp16(As0 + r * 136 + ch * 8, hsrc + (size_t)r * 512 + 0 * 128 + ch * 8);
            }
            cp_commit();
            // h1 -> buf1
            bsync(FRE1);
            for (int i = pid; i < 1024; i += 64) {
                int r = i >> 4, ch = i & 15;
                cp16((__nv_bfloat16*)((char*)As0 + AS_BYTES) + r * 136 + ch * 8,
                     hsrc + (size_t)r * 512 + 1 * 128 + ch * 8);
            }
            cp_commit();
            cp_wait<1>(); barrive(RDY0);    // h0 done
            // h2 -> buf0
            bsync(FRE0);
            for (int i = pid; i < 1024; i += 64) {
                int r = i >> 4, ch = i & 15;
                cp16(As0 + r * 136 + ch * 8, hsrc + (size_t)r * 512 + 2 * 128 + ch * 8);
            }
            cp_commit();
            cp_wait<1>(); barrive(RDY1);    // h1 done
            // h3 -> buf1
            bsync(FRE1);
            for (int i = pid; i < 1024; i += 64) {
                int r = i >> 4, ch = i & 15;
                cp16((__nv_bfloat16*)((char*)As0 + AS_BYTES) + r * 136 + ch * 8,
                     hsrc + (size_t)r * 512 + 3 * 128 + ch * 8);
            }
            cp_commit();
            cp_wait<1>(); barrive(RDY0);    // h2 done
            if (t < 511) {
                // xs(t+1) after consumers finish x_mma(t)
                bsync(FREX);
                for (int i = pid; i < 1024; i += 64) {
                    int r = i >> 4, ch = i & 15;
                    cp16(xs + r * 136 + ch * 8,
                         g_xb + ((size_t)(rbase + r) * 512 + (t + 1)) * 128 + ch * 8);
                }
                cp_commit();
                cp_wait<1>(); barrive(RDY1);  // h3 done
                cp_wait<0>(); barrive(RDYX);  // xs done
            } else {
                cp_wait<0>(); barrive(RDY1);  // h3 done
            }
        }
    }
}

// ---------------- projection + softmax ---------------------------------------
__global__ void proj_kernel(const float* __restrict__ Wp, const float* __restrict__ bp,
                            float* __restrict__ out) {
    __shared__ float hs[512];
    __shared__ float wred[8];
    int b = blockIdx.x, o = threadIdx.x;
    for (int i = o; i < 512; i += 128)
        hs[i] = fminf(fmaxf(g_hfinal[(size_t)b * 512 + i], -1.f), 1.f);
    __syncthreads();
    float acc = bp[o];
#pragma unroll 8
    for (int k = 0; k < 512; k++) acc = fmaf(hs[k], Wp[(size_t)k * 128 + o], acc);
    float m = acc;
#pragma unroll
    for (int s = 16; s > 0; s >>= 1) m = fmaxf(m, __shfl_xor_sync(0xffffffffu, m, s));
    int w = o >> 5, ln = o & 31;
    if (ln == 0) wred[w] = m;
    __syncthreads();
    m = fmaxf(fmaxf(wred[0], wred[1]), fmaxf(wred[2], wred[3]));
    float e = __expf(acc - m);
    float s = e;
#pragma unroll
    for (int sh = 16; sh > 0; sh >>= 1) s += __shfl_xor_sync(0xffffffffu, s, sh);
    if (ln == 0) wred[4 + w] = s;
    __syncthreads();
    s = wred[4] + wred[5] + wred[6] + wred[7];
    out[(size_t)b * 128 + o] = e * __fdividef(1.f, s);
}

// ---------------- launch ------------------------------------------------------
// Inputs resolved BY ELEMENT COUNT (all six sizes distinct):
//   x: 33554432, Wx: 262144, Wh: 1048576, b: 2048, Wp: 65536, bp: 128
extern "C" void kernel_launch(void* const* d_in, const int* in_sizes, int n_in,
                              void* d_out, int out_size) {
    (void)out_size;
    const float *x = 0, *Wx = 0, *Wh = 0, *b = 0, *Wp = 0, *bp = 0;
    for (int i = 0; i < n_in; i++) {
        switch (in_sizes[i]) {
            case 512 * 512 * 128: x  = (const float*)d_in[i]; break;
            case 128 * 2048:      Wx = (const float*)d_in[i]; break;
            case 512 * 2048:      Wh = (const float*)d_in[i]; break;
            case 2048:            b  = (const float*)d_in[i]; break;
            case 512 * 128:       Wp = (const float*)d_in[i]; break;
            case 128:             bp = (const float*)d_in[i]; break;
            default: break;
        }
    }
    float* out = (float*)d_out;

    cudaFuncSetAttribute(lstm_rec, cudaFuncAttributeMaxDynamicSharedMemorySize, REC_SMEM);

    conv_w<<<512, 256>>>(Wx, Wh);
    conv_x<<<512, 256>>>(x);
    reset_k<<<128, 256>>>();
    lstm_rec<<<NCTA, 320, REC_SMEM>>>(b);
    proj_kernel<<<512, 128>>>(Wp, bp, out);
}